// round 12
// baseline (speedup 1.0000x reference)
#include <cuda_runtime.h>
#include <cuda_bf16.h>
#include <cstdint>

// out[r] = W0 + b + sum_n x[r,n] * ( wlin[n] + D[r,n] ),
//   D[r,n] = sum_k x[r,k] * Q[k,n]   (Q upper-triangular)
// bf16 HMMA (mma.sync m16n8k16), split precision:
//   D = Xh*Bh + Xh*Bl + Xl*Bh,  B[n][k] = Q[k][n]
//
// R12: BM=128 / 128 thr / grid=256, launch_bounds(128,2) -> 2 CTAs/SM so the
// LDG+convert front-end of one CTA overlaps the MMA mainloop of the other.
// B tiles (bf16 hi/lo) hoisted to a 1-block prep kernel -> __device__ globals.

#define DIMS 64
#define BM   128
#define TPB  128
#define NBLK 256
#define ASTR 144               // smem bytes per row (128B data + 16B pad)

#define SM_WLIN 0              // 64 fp32
#define SM_W0B  256
#define SM_AH   512
#define SM_AL   (SM_AH + BM * ASTR)
#define SM_BH   (SM_AL + BM * ASTR)
#define SM_BL   (SM_BH + DIMS * ASTR)
#define SM_TOTAL (SM_BL + DIMS * ASTR)

__device__ __nv_bfloat16 g_Bh[DIMS * DIMS];
__device__ __nv_bfloat16 g_Bl[DIMS * DIMS];
__device__ float         g_wlin[DIMS];
__device__ float         g_w0b;

__global__ void prep_kernel(const float* __restrict__ W,
                            const float* __restrict__ bias)
{
    const int tid = threadIdx.x;          // 256 threads
    #pragma unroll
    for (int it = 0; it < 16; it++) {
        const int idx = tid + it * 256;   // 0..4095
        const int n = idx >> 6, k = idx & 63;
        float v = 0.0f;
        if (k <= n) {
            const int base = 1 + DIMS + k * DIMS - (k * (k - 1)) / 2;
            v = W[base + (n - k)];
        }
        const __nv_bfloat16 h = __float2bfloat16(v);
        g_Bh[idx] = h;
        g_Bl[idx] = __float2bfloat16(v - __bfloat162float(h));
    }
    if (tid < DIMS) g_wlin[tid] = W[1 + tid];
    if (tid == 0)   g_w0b = W[0] + bias[0];
}

__device__ __forceinline__ uint32_t smem_u32(const void* p) {
    uint32_t a;
    asm("{ .reg .u64 t; cvta.to.shared.u64 t, %1; cvt.u32.u64 %0, t; }"
        : "=r"(a) : "l"(p));
    return a;
}
__device__ __forceinline__ void ldsm_x4(uint32_t& a0, uint32_t& a1,
                                        uint32_t& a2, uint32_t& a3, uint32_t addr) {
    asm volatile("ldmatrix.sync.aligned.m8n8.x4.shared.b16 {%0,%1,%2,%3}, [%4];"
                 : "=r"(a0), "=r"(a1), "=r"(a2), "=r"(a3) : "r"(addr));
}
__device__ __forceinline__ void ldsm_x2(uint32_t& b0, uint32_t& b1, uint32_t addr) {
    asm volatile("ldmatrix.sync.aligned.m8n8.x2.shared.b16 {%0,%1}, [%2];"
                 : "=r"(b0), "=r"(b1) : "r"(addr));
}
__device__ __forceinline__ void mma16816(float* c, uint32_t a0, uint32_t a1,
                                         uint32_t a2, uint32_t a3,
                                         uint32_t b0, uint32_t b1) {
    asm volatile(
        "mma.sync.aligned.m16n8k16.row.col.f32.bf16.bf16.f32 "
        "{%0,%1,%2,%3}, {%4,%5,%6,%7}, {%8,%9}, {%0,%1,%2,%3};"
        : "+f"(c[0]), "+f"(c[1]), "+f"(c[2]), "+f"(c[3])
        : "r"(a0), "r"(a1), "r"(a2), "r"(a3), "r"(b0), "r"(b1));
}

__global__ void __launch_bounds__(TPB, 2)
poly_model_kernel(const float* __restrict__ x,
                  float* __restrict__ out)
{
    extern __shared__ char smem[];
    const uint32_t sb = smem_u32(smem);
    const int tid  = threadIdx.x;
    const int wid  = tid >> 5;
    const int lane = tid & 31;

    if (tid < DIMS)
        reinterpret_cast<float*>(smem + SM_WLIN)[tid] = g_wlin[tid];
    if (tid == 0)
        *reinterpret_cast<float*>(smem + SM_W0B) = g_w0b;

    // ---- B tiles: vector copy from prepped globals into padded rows ----
    // 4096 bf16 per tile = 512 uint4; 128 thr x 4 iters. 16B chunk c of row n.
    #pragma unroll
    for (int i = 0; i < 4; i++) {
        const int q  = tid + i * TPB;       // 0..511
        const int n  = q >> 3;              // row
        const int c  = q & 7;               // 16B chunk
        const int go = q * 16;              // byte offset in compact global
        const int so = n * ASTR + c * 16;
        *reinterpret_cast<uint4*>(smem + SM_BH + so) =
            *reinterpret_cast<const uint4*>(reinterpret_cast<const char*>(g_Bh) + go);
        *reinterpret_cast<uint4*>(smem + SM_BL + so) =
            *reinterpret_cast<const uint4*>(reinterpret_cast<const char*>(g_Bl) + go);
    }

    // ---- A tiles: coalesced fp32 LDG.128, split to bf16 hi/lo ----
    const float4* xg = reinterpret_cast<const float4*>(x)
                     + (size_t)blockIdx.x * BM * (DIMS / 4);
    #pragma unroll
    for (int i = 0; i < 16; i++) {
        const int q    = tid + i * TPB;     // 0..2047
        const float4 v = xg[q];
        const int row  = q >> 4;
        const int c4   = q & 15;

        __nv_bfloat162 h01 = __floats2bfloat162_rn(v.x, v.y);
        __nv_bfloat162 h23 = __floats2bfloat162_rn(v.z, v.w);
        const float2 f01 = __bfloat1622float2(h01);
        const float2 f23 = __bfloat1622float2(h23);
        __nv_bfloat162 l01 = __floats2bfloat162_rn(v.x - f01.x, v.y - f01.y);
        __nv_bfloat162 l23 = __floats2bfloat162_rn(v.z - f23.x, v.w - f23.y);

        const int off = row * ASTR + c4 * 8;
        uint2 hh, ll;
        hh.x = *reinterpret_cast<uint32_t*>(&h01);
        hh.y = *reinterpret_cast<uint32_t*>(&h23);
        ll.x = *reinterpret_cast<uint32_t*>(&l01);
        ll.y = *reinterpret_cast<uint32_t*>(&l23);
        *reinterpret_cast<uint2*>(smem + SM_AH + off) = hh;
        *reinterpret_cast<uint2*>(smem + SM_AL + off) = ll;
    }
    __syncthreads();

    // ---- warp MMA mainloop: warp owns 32 rows x 64 cols ----
    float acc[2][8][4];
    #pragma unroll
    for (int m = 0; m < 2; m++)
        #pragma unroll
        for (int n = 0; n < 8; n++)
            #pragma unroll
            for (int t = 0; t < 4; t++) acc[m][n][t] = 0.0f;

    const uint32_t aLane = (uint32_t)((((lane >> 3) & 1) * 8 + (lane & 7)) * ASTR
                                      + (lane >> 4) * 16);
    const uint32_t bLane = (uint32_t)((lane & 7) * ASTR + ((lane >> 3) & 1) * 16);
    const uint32_t aRow0 = (uint32_t)(wid * 32) * ASTR;

    const uint32_t aBase[3] = { sb + SM_AH, sb + SM_AH, sb + SM_AL };
    const uint32_t bBase[3] = { sb + SM_BH, sb + SM_BL, sb + SM_BH };

    #pragma unroll
    for (int pass = 0; pass < 3; pass++) {
        const uint32_t ab = aBase[pass] + aRow0 + aLane;
        const uint32_t bb = bBase[pass] + bLane;
        #pragma unroll
        for (int k = 0; k < 4; k++) {
            const uint32_t kbyte = k * 32;
            uint32_t bf[8][2];
            #pragma unroll
            for (int n = 0; n < 8; n++)
                ldsm_x2(bf[n][0], bf[n][1], bb + n * 8 * ASTR + kbyte);
            #pragma unroll
            for (int m = 0; m < 2; m++) {
                uint32_t a0, a1, a2, a3;
                ldsm_x4(a0, a1, a2, a3, ab + m * 16 * ASTR + kbyte);
                #pragma unroll
                for (int n = 0; n < 8; n++)
                    mma16816(acc[m][n], a0, a1, a2, a3, bf[n][0], bf[n][1]);
            }
        }
    }

    // ---- epilogue ----
    const float* wlin = reinterpret_cast<const float*>(smem + SM_WLIN);
    const float w0b   = *reinterpret_cast<const float*>(smem + SM_W0B);

    #pragma unroll
    for (int m = 0; m < 2; m++) {
        const int r0 = wid * 32 + m * 16 + (lane >> 2);
        const int r1 = r0 + 8;
        float p0 = 0.0f, p1 = 0.0f;
        #pragma unroll
        for (int n = 0; n < 8; n++) {
            const int c0 = n * 8 + (lane & 3) * 2;
            const float2 wl = *reinterpret_cast<const float2*>(&wlin[c0]);

            const int o0 = r0 * ASTR + c0 * 2;
            const int o1 = r1 * ASTR + c0 * 2;
            const float2 xh0 = __bfloat1622float2(
                *reinterpret_cast<const __nv_bfloat162*>(smem + SM_AH + o0));
            const float2 xl0 = __bfloat1622float2(
                *reinterpret_cast<const __nv_bfloat162*>(smem + SM_AL + o0));
            const float2 xh1 = __bfloat1622float2(
                *reinterpret_cast<const __nv_bfloat162*>(smem + SM_AH + o1));
            const float2 xl1 = __bfloat1622float2(
                *reinterpret_cast<const __nv_bfloat162*>(smem + SM_AL + o1));

            p0 = fmaf(xh0.x + xl0.x, acc[m][n][0] + wl.x, p0);
            p0 = fmaf(xh0.y + xl0.y, acc[m][n][1] + wl.y, p0);
            p1 = fmaf(xh1.x + xl1.x, acc[m][n][2] + wl.x, p1);
            p1 = fmaf(xh1.y + xl1.y, acc[m][n][3] + wl.y, p1);
        }
        p0 += __shfl_xor_sync(0xffffffffu, p0, 1);
        p0 += __shfl_xor_sync(0xffffffffu, p0, 2);
        p1 += __shfl_xor_sync(0xffffffffu, p1, 1);
        p1 += __shfl_xor_sync(0xffffffffu, p1, 2);
        if ((lane & 3) == 0) {
            const int gr = blockIdx.x * BM;
            out[gr + r0] = p0 + w0b;
            out[gr + r1] = p1 + w0b;
        }
    }
}

extern "C" void kernel_launch(void* const* d_in, const int* in_sizes, int n_in,
                              void* d_out, int out_size)
{
    const float* x    = (const float*)d_in[0];  // [32768, 64]
    const float* W    = (const float*)d_in[1];  // [2145]
    const float* bias = (const float*)d_in[2];  // [1]
    float* out = (float*)d_out;                 // [32768]

    prep_kernel<<<1, 256>>>(W, bias);
    cudaFuncSetAttribute(poly_model_kernel,
                         cudaFuncAttributeMaxDynamicSharedMemorySize, SM_TOTAL);
    poly_model_kernel<<<NBLK, TPB, SM_TOTAL>>>(x, out);
}

// round 13
// speedup vs baseline: 1.1776x; 1.1776x over previous
#include <cuda_runtime.h>
#include <cuda_bf16.h>
#include <cstdint>

// out[r] = W0 + b + sum_n x[r,n] * ( wlin[n] + D[r,n] ),
//   D[r,n] = sum_k x[r,k] * Q[k,n]   (Q upper-triangular)
// bf16 HMMA (m16n8k16), split precision: D = Xh*Bh + Xh*Bl + Xl*Bh.
//
// R13: single kernel. B-build overlapped with the in-flight A LDGs.
// wlin folded into MMA accumulator init. BM=128/TPB=128/grid=256, 2 CTAs/SM.

#define DIMS 64
#define BM   128
#define TPB  128
#define NBLK 256
#define ASTR 144               // smem bytes per row (128B data + 16B pad)

#define SM_WLIN 0              // 64 fp32
#define SM_W0B  256
#define SM_AH   512
#define SM_AL   (SM_AH + BM * ASTR)
#define SM_BH   (SM_AL + BM * ASTR)
#define SM_BL   (SM_BH + DIMS * ASTR)
#define SM_TOTAL (SM_BL + DIMS * ASTR)

__device__ __forceinline__ uint32_t smem_u32(const void* p) {
    uint32_t a;
    asm("{ .reg .u64 t; cvta.to.shared.u64 t, %1; cvt.u32.u64 %0, t; }"
        : "=r"(a) : "l"(p));
    return a;
}
__device__ __forceinline__ void ldsm_x4(uint32_t& a0, uint32_t& a1,
                                        uint32_t& a2, uint32_t& a3, uint32_t addr) {
    asm volatile("ldmatrix.sync.aligned.m8n8.x4.shared.b16 {%0,%1,%2,%3}, [%4];"
                 : "=r"(a0), "=r"(a1), "=r"(a2), "=r"(a3) : "r"(addr));
}
__device__ __forceinline__ void ldsm_x2(uint32_t& b0, uint32_t& b1, uint32_t addr) {
    asm volatile("ldmatrix.sync.aligned.m8n8.x2.shared.b16 {%0,%1}, [%2];"
                 : "=r"(b0), "=r"(b1) : "r"(addr));
}
__device__ __forceinline__ void mma16816(float* c, uint32_t a0, uint32_t a1,
                                         uint32_t a2, uint32_t a3,
                                         uint32_t b0, uint32_t b1) {
    asm volatile(
        "mma.sync.aligned.m16n8k16.row.col.f32.bf16.bf16.f32 "
        "{%0,%1,%2,%3}, {%4,%5,%6,%7}, {%8,%9}, {%0,%1,%2,%3};"
        : "+f"(c[0]), "+f"(c[1]), "+f"(c[2]), "+f"(c[3])
        : "r"(a0), "r"(a1), "r"(a2), "r"(a3), "r"(b0), "r"(b1));
}

__global__ void __launch_bounds__(TPB, 2)
poly_model_kernel(const float* __restrict__ x,
                  const float* __restrict__ W,
                  const float* __restrict__ bias,
                  float* __restrict__ out)
{
    extern __shared__ char smem[];
    const uint32_t sb = smem_u32(smem);
    const int tid  = threadIdx.x;
    const int wid  = tid >> 5;
    const int lane = tid & 31;

    // ---- issue all 16 A-tile LDG.128 first (latency covered by B-build) ----
    const float4* xg = reinterpret_cast<const float4*>(x)
                     + (size_t)blockIdx.x * BM * (DIMS / 4);
    float4 v[16];
    #pragma unroll
    for (int i = 0; i < 16; i++)
        v[i] = xg[tid + i * TPB];

    if (tid < DIMS)
        reinterpret_cast<float*>(smem + SM_WLIN)[tid] = W[1 + tid];
    if (tid == 0)
        *reinterpret_cast<float*>(smem + SM_W0B) = W[0] + bias[0];

    // ---- B tiles while A loads are in flight: B[n][k]=Q[k][n], bf16 hi/lo ----
    #pragma unroll
    for (int it = 0; it < 32; it++) {
        const int idx = tid + it * TPB;          // 0..4095
        const int n = idx >> 6, k = idx & 63;
        float bv = 0.0f;
        if (k <= n) {
            const int base = 1 + DIMS + k * DIMS - (k * (k - 1)) / 2;
            bv = W[base + (n - k)];
        }
        const __nv_bfloat16 h = __float2bfloat16(bv);
        const __nv_bfloat16 l = __float2bfloat16(bv - __bfloat162float(h));
        const int off = n * ASTR + k * 2;
        *reinterpret_cast<__nv_bfloat16*>(smem + SM_BH + off) = h;
        *reinterpret_cast<__nv_bfloat16*>(smem + SM_BL + off) = l;
    }

    // ---- consume A loads: split to bf16 hi/lo, store padded rows ----
    #pragma unroll
    for (int i = 0; i < 16; i++) {
        const int q   = tid + i * TPB;
        const int row = q >> 4;
        const int c4  = q & 15;

        __nv_bfloat162 h01 = __floats2bfloat162_rn(v[i].x, v[i].y);
        __nv_bfloat162 h23 = __floats2bfloat162_rn(v[i].z, v[i].w);
        const float2 f01 = __bfloat1622float2(h01);
        const float2 f23 = __bfloat1622float2(h23);
        __nv_bfloat162 l01 = __floats2bfloat162_rn(v[i].x - f01.x, v[i].y - f01.y);
        __nv_bfloat162 l23 = __floats2bfloat162_rn(v[i].z - f23.x, v[i].w - f23.y);

        const int off = row * ASTR + c4 * 8;
        uint2 hh, ll;
        hh.x = *reinterpret_cast<uint32_t*>(&h01);
        hh.y = *reinterpret_cast<uint32_t*>(&h23);
        ll.x = *reinterpret_cast<uint32_t*>(&l01);
        ll.y = *reinterpret_cast<uint32_t*>(&l23);
        *reinterpret_cast<uint2*>(smem + SM_AH + off) = hh;
        *reinterpret_cast<uint2*>(smem + SM_AL + off) = ll;
    }
    __syncthreads();

    // ---- accumulators init with wlin (D_init[r,c] = wlin[c]) ----
    const float* wlin = reinterpret_cast<const float*>(smem + SM_WLIN);
    float acc[2][8][4];
    #pragma unroll
    for (int n = 0; n < 8; n++) {
        const float2 wl = *reinterpret_cast<const float2*>(
            &wlin[n * 8 + (lane & 3) * 2]);
        #pragma unroll
        for (int m = 0; m < 2; m++) {
            acc[m][n][0] = wl.x; acc[m][n][1] = wl.y;
            acc[m][n][2] = wl.x; acc[m][n][3] = wl.y;
        }
    }

    // ---- warp MMA mainloop: warp owns 32 rows x 64 cols ----
    const uint32_t aLane = (uint32_t)((((lane >> 3) & 1) * 8 + (lane & 7)) * ASTR
                                      + (lane >> 4) * 16);
    const uint32_t bLane = (uint32_t)((lane & 7) * ASTR + ((lane >> 3) & 1) * 16);
    const uint32_t aRow0 = (uint32_t)(wid * 32) * ASTR;

    const uint32_t aBase[3] = { sb + SM_AH, sb + SM_AH, sb + SM_AL };
    const uint32_t bBase[3] = { sb + SM_BH, sb + SM_BL, sb + SM_BH };

    #pragma unroll
    for (int pass = 0; pass < 3; pass++) {
        const uint32_t ab = aBase[pass] + aRow0 + aLane;
        const uint32_t bb = bBase[pass] + bLane;
        #pragma unroll
        for (int k = 0; k < 4; k++) {
            const uint32_t kbyte = k * 32;
            uint32_t bf[8][2];
            #pragma unroll
            for (int n = 0; n < 8; n++)
                ldsm_x2(bf[n][0], bf[n][1], bb + n * 8 * ASTR + kbyte);
            #pragma unroll
            for (int m = 0; m < 2; m++) {
                uint32_t a0, a1, a2, a3;
                ldsm_x4(a0, a1, a2, a3, ab + m * 16 * ASTR + kbyte);
                #pragma unroll
                for (int n = 0; n < 8; n++)
                    mma16816(acc[m][n], a0, a1, a2, a3, bf[n][0], bf[n][1]);
            }
        }
    }

    // ---- epilogue: out[r] = sum_c x[c]*acc[c] + W0 + b ----
    const float w0b = *reinterpret_cast<const float*>(smem + SM_W0B);

    #pragma unroll
    for (int m = 0; m < 2; m++) {
        const int r0 = wid * 32 + m * 16 + (lane >> 2);
        const int r1 = r0 + 8;
        float p0 = 0.0f, p1 = 0.0f;
        #pragma unroll
        for (int n = 0; n < 8; n++) {
            const int c0 = n * 8 + (lane & 3) * 2;
            const int o0 = r0 * ASTR + c0 * 2;
            const int o1 = r1 * ASTR + c0 * 2;
            const float2 xh0 = __bfloat1622float2(
                *reinterpret_cast<const __nv_bfloat162*>(smem + SM_AH + o0));
            const float2 xl0 = __bfloat1622float2(
                *reinterpret_cast<const __nv_bfloat162*>(smem + SM_AL + o0));
            const float2 xh1 = __bfloat1622float2(
                *reinterpret_cast<const __nv_bfloat162*>(smem + SM_AH + o1));
            const float2 xl1 = __bfloat1622float2(
                *reinterpret_cast<const __nv_bfloat162*>(smem + SM_AL + o1));

            p0 = fmaf(xh0.x + xl0.x, acc[m][n][0], p0);
            p0 = fmaf(xh0.y + xl0.y, acc[m][n][1], p0);
            p1 = fmaf(xh1.x + xl1.x, acc[m][n][2], p1);
            p1 = fmaf(xh1.y + xl1.y, acc[m][n][3], p1);
        }
        p0 += __shfl_xor_sync(0xffffffffu, p0, 1);
        p0 += __shfl_xor_sync(0xffffffffu, p0, 2);
        p1 += __shfl_xor_sync(0xffffffffu, p1, 1);
        p1 += __shfl_xor_sync(0xffffffffu, p1, 2);
        if ((lane & 3) == 0) {
            const int gr = blockIdx.x * BM;
            out[gr + r0] = p0 + w0b;
            out[gr + r1] = p1 + w0b;
        }
    }
}

extern "C" void kernel_launch(void* const* d_in, const int* in_sizes, int n_in,
                              void* d_out, int out_size)
{
    const float* x    = (const float*)d_in[0];  // [32768, 64]
    const float* W    = (const float*)d_in[1];  // [2145]
    const float* bias = (const float*)d_in[2];  // [1]
    float* out = (float*)d_out;                 // [32768]

    cudaFuncSetAttribute(poly_model_kernel,
                         cudaFuncAttributeMaxDynamicSharedMemorySize, SM_TOTAL);
    poly_model_kernel<<<NBLK, TPB, SM_TOTAL>>>(x, W, bias, out);
}